// round 3
// baseline (speedup 1.0000x reference)
#include <cuda_runtime.h>

// GCN 2-layer: x[N,3] -> W1[3,16] -> relu -> W2[16,3] -> out[N,3]
// norm trick: hs = (x@W)*dinv ; acc[d] += hs[s] over edges (+ self via init acc=hs);
// out = acc*dinv + b.

#define NMAX 200000

__device__ float g_deg [NMAX];
__device__ float g_dinv[NMAX];
__device__ float g_hs1 [NMAX * 16];
__device__ float g_acc1[NMAX * 16];
__device__ float g_hs2 [NMAX * 3];

__global__ void k_deg_init(int n) {
    int i = blockIdx.x * blockDim.x + threadIdx.x;
    if (i < n) g_deg[i] = 1.0f;   // self loop
}

__global__ void k_deg_edges(const int* __restrict__ dst, int E) {
    int e = blockIdx.x * blockDim.x + threadIdx.x;
    if (e < E) atomicAdd(&g_deg[dst[e]], 1.0f);
}

// per-node: dinv, hs1 = (x@W1)*dinv, acc1 = hs1 (self loop)
__global__ void k_layer1_node(const float* __restrict__ x,
                              const float* __restrict__ W1, int n) {
    int i = blockIdx.x * blockDim.x + threadIdx.x;
    if (i >= n) return;
    float dv = rsqrtf(g_deg[i]);
    g_dinv[i] = dv;
    float x0 = x[i * 3 + 0], x1 = x[i * 3 + 1], x2 = x[i * 3 + 2];
#pragma unroll
    for (int f = 0; f < 16; f++) {
        float h = x0 * __ldg(&W1[f]) + x1 * __ldg(&W1[16 + f]) + x2 * __ldg(&W1[32 + f]);
        float hs = h * dv;
        g_hs1[i * 16 + f]  = hs;
        g_acc1[i * 16 + f] = hs;
    }
}

// 4 threads per edge: each lane handles 4 features via float4 gather + v4 red.
// 16B-aligned (node*16 floats + lane*4 floats).
__global__ void k_scatter1(const int* __restrict__ src,
                           const int* __restrict__ dst, int E) {
    long long t = (long long)blockIdx.x * blockDim.x + threadIdx.x;
    int e = (int)(t >> 2);
    int f4 = (int)(t & 3);
    if (e >= E) return;
    int s = src[e], d = dst[e];
    const float4 v = *reinterpret_cast<const float4*>(&g_hs1[(long long)s * 16 + f4 * 4]);
    float* p = &g_acc1[(long long)d * 16 + f4 * 4];
    asm volatile("red.global.add.v4.f32 [%0], {%1, %2, %3, %4};"
                 :: "l"(p), "f"(v.x), "f"(v.y), "f"(v.z), "f"(v.w)
                 : "memory");
}

// per-node: v = relu(acc1*dinv + b1); hs2 = (v@W2)*dinv; out init = hs2 (self loop)
__global__ void k_layer2_node(const float* __restrict__ b1,
                              const float* __restrict__ W2,
                              float* __restrict__ out, int n) {
    int i = blockIdx.x * blockDim.x + threadIdx.x;
    if (i >= n) return;
    float dv = g_dinv[i];
    float v[16];
#pragma unroll
    for (int f = 0; f < 16; f++)
        v[f] = fmaxf(g_acc1[i * 16 + f] * dv + __ldg(&b1[f]), 0.0f);
#pragma unroll
    for (int c = 0; c < 3; c++) {
        float h = 0.0f;
#pragma unroll
        for (int f = 0; f < 16; f++) h += v[f] * __ldg(&W2[f * 3 + c]);
        float hs = h * dv;
        g_hs2[i * 3 + c] = hs;
        out[i * 3 + c]   = hs;
    }
}

// 4 threads per edge (feature 0..2 live, lane 3 idle) for coalescing
__global__ void k_scatter2(const int* __restrict__ src,
                           const int* __restrict__ dst,
                           float* __restrict__ out, int E) {
    long long t = (long long)blockIdx.x * blockDim.x + threadIdx.x;
    int e = (int)(t >> 2);
    int f = (int)(t & 3);
    if (e >= E || f >= 3) return;
    int s = src[e], d = dst[e];
    atomicAdd(&out[(long long)d * 3 + f], g_hs2[(long long)s * 3 + f]);
}

__global__ void k_final(const float* __restrict__ b2,
                        float* __restrict__ out, int n3) {
    int i = blockIdx.x * blockDim.x + threadIdx.x;
    if (i >= n3) return;
    int node = i / 3;
    int c = i - node * 3;
    out[i] = out[i] * g_dinv[node] + __ldg(&b2[c]);
}

extern "C" void kernel_launch(void* const* d_in, const int* in_sizes, int n_in,
                              void* d_out, int out_size) {
    const float* x  = (const float*)d_in[0];
    const int*   ei = (const int*)  d_in[1];
    const float* W1 = (const float*)d_in[2];
    const float* b1 = (const float*)d_in[3];
    const float* W2 = (const float*)d_in[4];
    const float* b2 = (const float*)d_in[5];
    float* out = (float*)d_out;

    int n = in_sizes[0] / 3;
    int E = in_sizes[1] / 2;
    const int* src = ei;
    const int* dst = ei + E;

    const int B = 256;
    int gn = (n + B - 1) / B;

    k_deg_init<<<gn, B>>>(n);
    k_deg_edges<<<(E + B - 1) / B, B>>>(dst, E);
    k_layer1_node<<<gn, B>>>(x, W1, n);
    {
        long long tot = (long long)E * 4;
        int g = (int)((tot + B - 1) / B);
        k_scatter1<<<g, B>>>(src, dst, E);
    }
    k_layer2_node<<<gn, B>>>(b1, W2, out, n);
    {
        long long tot = (long long)E * 4;
        int g = (int)((tot + B - 1) / B);
        k_scatter2<<<g, B>>>(src, dst, out, E);
    }
    k_final<<<(n * 3 + B - 1) / B, B>>>(b2, out, n * 3);
}